// round 1
// baseline (speedup 1.0000x reference)
#include <cuda_runtime.h>
#include <mma.h>

using namespace nvcuda;

#define B_  4
#define T_  4096
#define D_  1024
#define N_  2048
#define L_  768
#define H_  16
#define DH  64
#define NSEG 8

// ---------------- scratch (static device globals; no allocation) ----------------
__device__ float g_nx1[(size_t)B_ * T_ * D_];          // 16.8M
__device__ float g_nx2[(size_t)B_ * N_ * L_];          // 6.3M
__device__ float g_q  [(size_t)B_ * T_ * D_];          // 16.8M
__device__ float g_k  [(size_t)B_ * N_ * D_];          // 8.4M
__device__ float g_v  [(size_t)B_ * N_ * D_];          // 8.4M
__device__ float g_ap [(size_t)NSEG * B_ * H_ * DH * DH]; // 2.1M split-N partials
__device__ float g_attn[(size_t)B_ * H_ * DH * DH];    // 262K

// ---------------- LayerNorm: one row per block, 256 threads ----------------
__global__ void __launch_bounds__(256) ln_kernel(const float* __restrict__ x,
                                                 const float* __restrict__ g,
                                                 const float* __restrict__ bb,
                                                 float* __restrict__ out, int D) {
    int row = blockIdx.x;
    const float* xr = x + (size_t)row * D;
    int cnt = D >> 8;          // 4 for D=1024, 3 for D=768
    float v[4];
    float s = 0.f, s2 = 0.f;
    for (int i = 0; i < cnt; i++) {
        v[i] = xr[threadIdx.x + (i << 8)];
        s += v[i];
        s2 += v[i] * v[i];
    }
    #pragma unroll
    for (int o = 16; o; o >>= 1) {
        s  += __shfl_xor_sync(0xffffffffu, s, o);
        s2 += __shfl_xor_sync(0xffffffffu, s2, o);
    }
    __shared__ float sa[8], sb[8];
    int w = threadIdx.x >> 5, lane = threadIdx.x & 31;
    if (lane == 0) { sa[w] = s; sb[w] = s2; }
    __syncthreads();
    if (w == 0) {
        s  = (lane < 8) ? sa[lane] : 0.f;
        s2 = (lane < 8) ? sb[lane] : 0.f;
        #pragma unroll
        for (int o = 4; o; o >>= 1) {
            s  += __shfl_xor_sync(0xffffffffu, s, o);
            s2 += __shfl_xor_sync(0xffffffffu, s2, o);
        }
        if (lane == 0) { sa[0] = s; sb[0] = s2; }
    }
    __syncthreads();
    float invD = 1.f / (float)D;
    float mu  = sa[0] * invD;
    float var = sb[0] * invD - mu * mu;
    float inv = rsqrtf(var + 1e-5f);
    float* orow = out + (size_t)row * D;
    for (int i = 0; i < cnt; i++) {
        int c = threadIdx.x + (i << 8);
        orow[c] = (v[i] - mu) * inv * g[c] + bb[c];
    }
}

// ---------------- GEMM: C[M,N] = A[M,K] @ W[K,N], tf32 wmma ----------------
// BM=128 BN=128 BK=32, 256 threads (8 warps in 2x4), warp tile 64x32.
__global__ void __launch_bounds__(256) gemm_tf32(const float* __restrict__ A,
                                                 const float* __restrict__ W,
                                                 float* __restrict__ C,
                                                 int M, int N, int K) {
    __shared__ float As[128][40];   // padded, row = 160B (32B-aligned)
    __shared__ float Bs[32][136];   // padded, row = 544B (32B-aligned)
    int bm = blockIdx.y * 128, bn = blockIdx.x * 128;
    int tid = threadIdx.x;
    int wid = tid >> 5;
    int wm = (wid >> 2) * 64, wn = (wid & 3) * 32;

    wmma::fragment<wmma::accumulator, 16, 16, 8, float> acc[4][2];
    #pragma unroll
    for (int i = 0; i < 4; i++)
        #pragma unroll
        for (int j = 0; j < 2; j++) wmma::fill_fragment(acc[i][j], 0.f);

    for (int k0 = 0; k0 < K; k0 += 32) {
        #pragma unroll
        for (int i = 0; i < 4; i++) {
            int idx = tid + i * 256;
            int r = idx >> 3, c = (idx & 7) << 2;
            float4 t = *(const float4*)(A + (size_t)(bm + r) * K + k0 + c);
            float4 u;
            u.x = wmma::__float_to_tf32(t.x);
            u.y = wmma::__float_to_tf32(t.y);
            u.z = wmma::__float_to_tf32(t.z);
            u.w = wmma::__float_to_tf32(t.w);
            *(float4*)&As[r][c] = u;
        }
        #pragma unroll
        for (int i = 0; i < 4; i++) {
            int idx = tid + i * 256;
            int r = idx >> 5, c = (idx & 31) << 2;
            float4 t = *(const float4*)(W + (size_t)(k0 + r) * N + bn + c);
            float4 u;
            u.x = wmma::__float_to_tf32(t.x);
            u.y = wmma::__float_to_tf32(t.y);
            u.z = wmma::__float_to_tf32(t.z);
            u.w = wmma::__float_to_tf32(t.w);
            *(float4*)&Bs[r][c] = u;
        }
        __syncthreads();
        #pragma unroll
        for (int kk = 0; kk < 32; kk += 8) {
            wmma::fragment<wmma::matrix_a, 16, 16, 8, wmma::precision::tf32, wmma::row_major> af[4];
            wmma::fragment<wmma::matrix_b, 16, 16, 8, wmma::precision::tf32, wmma::row_major> bf[2];
            #pragma unroll
            for (int i = 0; i < 4; i++)
                wmma::load_matrix_sync(af[i], &As[wm + 16 * i][kk], 40);
            #pragma unroll
            for (int j = 0; j < 2; j++)
                wmma::load_matrix_sync(bf[j], &Bs[kk][wn + 16 * j], 136);
            #pragma unroll
            for (int i = 0; i < 4; i++)
                #pragma unroll
                for (int j = 0; j < 2; j++)
                    wmma::mma_sync(acc[i][j], af[i], bf[j], acc[i][j]);
        }
        __syncthreads();
    }
    #pragma unroll
    for (int i = 0; i < 4; i++)
        #pragma unroll
        for (int j = 0; j < 2; j++)
            wmma::store_matrix_sync(C + (size_t)(bm + wm + 16 * i) * N + bn + wn + 16 * j,
                                    acc[i][j], N, wmma::mem_row_major);
}

// ---------------- bias + per-head softmax over 64-chunks (in place) ----------------
// rows of 1024 cols = 16 heads * 64; block = 512 threads = 16 warps, 1 warp per head
__global__ void __launch_bounds__(512) softmax64_kernel(float* __restrict__ buf,
                                                        const float* __restrict__ bias) {
    int row = blockIdx.x;
    int w = threadIdx.x >> 5, lane = threadIdx.x & 31;
    float* p = buf + (size_t)row * 1024 + w * 64;
    float a = p[lane]      + bias[w * 64 + lane];
    float b = p[lane + 32] + bias[w * 64 + lane + 32];
    float m = fmaxf(a, b);
    #pragma unroll
    for (int o = 16; o; o >>= 1) m = fmaxf(m, __shfl_xor_sync(0xffffffffu, m, o));
    float ea = __expf(a - m), eb = __expf(b - m);
    float s = ea + eb;
    #pragma unroll
    for (int o = 16; o; o >>= 1) s += __shfl_xor_sync(0xffffffffu, s, o);
    float inv = 1.f / s;
    p[lane]      = ea * inv;
    p[lane + 32] = eb * inv;
}

// ---------------- bias add (V): one row per block ----------------
__global__ void __launch_bounds__(256) addbias_kernel(float* __restrict__ v,
                                                      const float* __restrict__ b) {
    float* p = v + (size_t)blockIdx.x * 1024;
    #pragma unroll
    for (int i = 0; i < 4; i++) {
        int c = threadIdx.x + (i << 8);
        p[c] += b[c];
    }
}

// ---------------- attn partials: attn[b,h,d,l] = sum_n k[b,n,h,d]*v[b,n,h,l] ----------------
// grid (B*H, NSEG); each block reduces its 256-n segment into a private partial slab.
__global__ void __launch_bounds__(256) attn_part_kernel(const float* __restrict__ k,
                                                        const float* __restrict__ v,
                                                        float* __restrict__ ap) {
    __shared__ float ks[32][68], vs[32][68];
    int bh = blockIdx.x;
    int b = bh >> 4, h = bh & 15;
    int seg = blockIdx.y;
    int tid = threadIdx.x;
    int d0 = (tid >> 4) << 2, l0 = (tid & 15) << 2;
    float acc[4][4];
    #pragma unroll
    for (int i = 0; i < 4; i++)
        #pragma unroll
        for (int j = 0; j < 4; j++) acc[i][j] = 0.f;

    const float* kb = k + (size_t)(b * N_) * D_ + h * 64;
    const float* vb = v + (size_t)(b * N_) * D_ + h * 64;
    int nend = seg * 256 + 256;
    for (int n0 = seg * 256; n0 < nend; n0 += 32) {
        #pragma unroll
        for (int i = 0; i < 2; i++) {
            int idx = tid + i * 256;
            int r = idx >> 4, c = (idx & 15) << 2;
            *(float4*)&ks[r][c] = *(const float4*)(kb + (size_t)(n0 + r) * D_ + c);
            *(float4*)&vs[r][c] = *(const float4*)(vb + (size_t)(n0 + r) * D_ + c);
        }
        __syncthreads();
        #pragma unroll 8
        for (int n = 0; n < 32; n++) {
            float kr[4], vr[4];
            #pragma unroll
            for (int i = 0; i < 4; i++) { kr[i] = ks[n][d0 + i]; vr[i] = vs[n][l0 + i]; }
            #pragma unroll
            for (int i = 0; i < 4; i++)
                #pragma unroll
                for (int j = 0; j < 4; j++) acc[i][j] += kr[i] * vr[j];
        }
        __syncthreads();
    }
    float* dst = ap + ((size_t)seg * (B_ * H_) + bh) * 4096;
    #pragma unroll
    for (int i = 0; i < 4; i++)
        #pragma unroll
        for (int j = 0; j < 4; j++) dst[(d0 + i) * 64 + l0 + j] = acc[i][j];
}

// deterministic partial reduce: 65536 threads x 4 elems
__global__ void __launch_bounds__(256) attn_reduce_kernel(const float* __restrict__ ap,
                                                          float* __restrict__ attn) {
    int i = blockIdx.x * blockDim.x + threadIdx.x;
    #pragma unroll
    for (int r = 0; r < 4; r++) {
        int j = i + r * 65536;
        float s = 0.f;
        #pragma unroll
        for (int sg = 0; sg < NSEG; sg++) s += ap[(size_t)sg * (B_ * H_ * 4096) + j];
        attn[j] = s;
    }
}

// ---------------- final: out = Ch + bh + q @ attn  (per b,h,64-t tile) ----------------
__global__ void __launch_bounds__(256) final_kernel(const float* __restrict__ Ch,
                                                    const float* __restrict__ bh,
                                                    const float* __restrict__ q,
                                                    const float* __restrict__ attn,
                                                    float* __restrict__ out) {
    __shared__ float sA[64][64];
    __shared__ float sQ[64][68];
    int t0 = blockIdx.x * 64, h = blockIdx.y, b = blockIdx.z;
    int tid = threadIdx.x;
    const float* ap = attn + (size_t)(b * H_ + h) * 4096;
    #pragma unroll
    for (int i = 0; i < 4; i++) {
        int idx = tid + i * 256;
        int r = idx >> 4, c = (idx & 15) << 2;
        *(float4*)&sA[r][c] = *(const float4*)(ap + r * 64 + c);
    }
    #pragma unroll
    for (int i = 0; i < 4; i++) {
        int idx = tid + i * 256;
        int r = idx >> 4, c = (idx & 15) << 2;
        *(float4*)&sQ[r][c] = *(const float4*)(q + (size_t)(b * T_ + t0 + r) * D_ + h * 64 + c);
    }
    __syncthreads();
    int tl = tid >> 2, l0 = (tid & 3) << 4;
    float accv[16];
    #pragma unroll
    for (int j = 0; j < 16; j++) accv[j] = 0.f;
    #pragma unroll 4
    for (int d = 0; d < 64; d++) {
        float qd = sQ[tl][d];
        #pragma unroll
        for (int jj = 0; jj < 4; jj++) {
            float4 a4 = *(const float4*)&sA[d][l0 + jj * 4];
            accv[jj * 4 + 0] += qd * a4.x;
            accv[jj * 4 + 1] += qd * a4.y;
            accv[jj * 4 + 2] += qd * a4.z;
            accv[jj * 4 + 3] += qd * a4.w;
        }
    }
    size_t base = (size_t)(b * T_ + t0 + tl) * D_ + h * 64 + l0;
    #pragma unroll
    for (int j = 0; j < 16; j++)
        out[base + j] = Ch[base + j] + bh[h * 64 + l0 + j] + accv[j];
}

// ---------------- launch ----------------
extern "C" void kernel_launch(void* const* d_in, const int* in_sizes, int n_in,
                              void* d_out, int out_size) {
    const float* x1 = (const float*)d_in[0];
    const float* x2 = (const float*)d_in[1];
    const float* Wq = (const float*)d_in[2];
    const float* bq = (const float*)d_in[3];
    const float* Wk = (const float*)d_in[4];
    const float* bk = (const float*)d_in[5];
    const float* Wv = (const float*)d_in[6];
    const float* bv = (const float*)d_in[7];
    const float* Wh = (const float*)d_in[8];
    const float* bh = (const float*)d_in[9];
    const float* g1 = (const float*)d_in[10];
    const float* b1 = (const float*)d_in[11];
    const float* g2 = (const float*)d_in[12];
    const float* b2 = (const float*)d_in[13];
    float* out = (float*)d_out;

    float *nx1, *nx2, *q, *k, *v, *ap, *attn;
    cudaGetSymbolAddress((void**)&nx1, g_nx1);
    cudaGetSymbolAddress((void**)&nx2, g_nx2);
    cudaGetSymbolAddress((void**)&q,   g_q);
    cudaGetSymbolAddress((void**)&k,   g_k);
    cudaGetSymbolAddress((void**)&v,   g_v);
    cudaGetSymbolAddress((void**)&ap,  g_ap);
    cudaGetSymbolAddress((void**)&attn, g_attn);

    // LayerNorms
    ln_kernel<<<B_ * T_, 256>>>(x1, g1, b1, nx1, D_);
    ln_kernel<<<B_ * N_, 256>>>(x2, g2, b2, nx2, L_);

    // Q = nx1 @ Wq ; softmax(+bq) per head
    gemm_tf32<<<dim3(D_ / 128, (B_ * T_) / 128), 256>>>(nx1, Wq, q, B_ * T_, D_, D_);
    softmax64_kernel<<<B_ * T_, 512>>>(q, bq);

    // K = nx2 @ Wk ; softmax(+bk) per head
    gemm_tf32<<<dim3(D_ / 128, (B_ * N_) / 128), 256>>>(nx2, Wk, k, B_ * N_, D_, L_);
    softmax64_kernel<<<B_ * N_, 512>>>(k, bk);

    // V = nx2 @ Wv + bv
    gemm_tf32<<<dim3(D_ / 128, (B_ * N_) / 128), 256>>>(nx2, Wv, v, B_ * N_, D_, L_);
    addbias_kernel<<<B_ * N_, 256>>>(v, bv);

    // attn = k^T v per (b,h): split-N partials then deterministic reduce
    attn_part_kernel<<<dim3(B_ * H_, NSEG), 256>>>(k, v, ap);
    attn_reduce_kernel<<<256, 256>>>(ap, attn);

    // out = x1 @ Wh, then += bh + q @ attn
    gemm_tf32<<<dim3(D_ / 128, (B_ * T_) / 128), 256>>>(x1, Wh, out, B_ * T_, D_, D_);
    final_kernel<<<dim3(T_ / 64, H_, B_), 256>>>(out, bh, q, attn, out);
}